// round 5
// baseline (speedup 1.0000x reference)
#include <cuda_runtime.h>
#include <cuda_fp16.h>
#include <cstdint>
#include <cstddef>

// ---------------- problem constants ----------------
namespace {
constexpr int kN1 = 67584;
constexpr int kN2 = 6144;
constexpr int kN3 = 1024;
constexpr int kFIN = 100;
constexpr int kHID = 256;
constexpr int kOUT = 47;
constexpr int kFAN2 = 10;
constexpr int kFAN3 = 5;
constexpr int K1P = 224;   // layer-1 K padded (agg 100 | dst 100 | zeros 24)
constexpr int K2P = 512;   // layer-2/3 K (agg 256 | dst 256)
}  // namespace

// ---------------- scratch (device globals) ----------------------------------
__device__ __half g_h1[(size_t)kN1 * kHID];
__device__ __half g_A2[(size_t)kN2 * K2P];
__device__ __half g_h2[(size_t)kN2 * kHID];
__device__ __half g_A3[(size_t)kN3 * K2P];
__device__ __half g_W1t[(size_t)256 * K1P];   // [N][K], transposed
__device__ __half g_W2t[(size_t)256 * K2P];
__device__ __half g_W3t[(size_t)64  * K2P];
__device__ int g_is64;

// ---------------- PTX helpers ------------------------------------------------
__device__ __forceinline__ uint32_t smem_u32(const void* p) {
    uint32_t a;
    asm("{ .reg .u64 t; cvta.to.shared.u64 t, %1; cvt.u32.u64 %0, t; }" : "=r"(a) : "l"(p));
    return a;
}
__device__ __forceinline__ void cpasync16(uint32_t saddr, const void* g) {
    asm volatile("cp.async.cg.shared.global [%0], [%1], 16;" :: "r"(saddr), "l"(g) : "memory");
}
__device__ __forceinline__ void ldm_x4(uint32_t& r0, uint32_t& r1, uint32_t& r2, uint32_t& r3,
                                       uint32_t addr) {
    asm volatile("ldmatrix.sync.aligned.m8n8.x4.shared.b16 {%0,%1,%2,%3}, [%4];"
                 : "=r"(r0), "=r"(r1), "=r"(r2), "=r"(r3) : "r"(addr));
}
__device__ __forceinline__ void ldm_x2(uint32_t& r0, uint32_t& r1, uint32_t addr) {
    asm volatile("ldmatrix.sync.aligned.m8n8.x2.shared.b16 {%0,%1}, [%2];"
                 : "=r"(r0), "=r"(r1) : "r"(addr));
}
__device__ __forceinline__ void mma16816(float* c, const uint32_t* a, uint32_t b0, uint32_t b1) {
    asm volatile(
        "mma.sync.aligned.m16n8k16.row.col.f32.f16.f16.f32 "
        "{%0,%1,%2,%3}, {%4,%5,%6,%7}, {%8,%9}, {%0,%1,%2,%3};"
        : "+f"(c[0]), "+f"(c[1]), "+f"(c[2]), "+f"(c[3])
        : "r"(a[0]), "r"(a[1]), "r"(a[2]), "r"(a[3]), "r"(b0), "r"(b1));
}
__device__ __forceinline__ long long load_index(const void* p, long long i, int is64) {
    return is64 ? ((const long long*)p)[i] : (long long)((const int*)p)[i];
}

// ---------------- pack weights (fp16, transposed [N][K]) ---------------------
__global__ void pack_weights(const float* __restrict__ Wl1, const float* __restrict__ Wr1,
                             const float* __restrict__ Wl2, const float* __restrict__ Wr2,
                             const float* __restrict__ Wl3, const float* __restrict__ Wr3,
                             const void* __restrict__ dst1) {
    int i = blockIdx.x * blockDim.x + threadIdx.x;
    if (i == 0) g_is64 = (((const long long*)dst1)[15] == 1LL) ? 1 : 0;

    if (i < 256 * K1P) {  // W1t
        int n = i / K1P, k = i % K1P;
        float w = 0.f;
        if (k < kFIN) w = Wl1[k * kHID + n];
        else if (k < 2 * kFIN) w = Wr1[(k - kFIN) * kHID + n];
        g_W1t[i] = __float2half_rn(w);
    }
    if (i < 256 * K2P) {  // W2t
        int n = i / K2P, k = i % K2P;
        float w = (k < kHID) ? Wl2[k * kHID + n] : Wr2[(k - kHID) * kHID + n];
        g_W2t[i] = __float2half_rn(w);
    }
    if (i < 64 * K2P) {  // W3t (N padded 47 -> 64)
        int n = i / K2P, k = i % K2P;
        float w = 0.f;
        if (n < kOUT) w = (k < kHID) ? Wl3[k * kOUT + n] : Wr3[(k - kHID) * kOUT + n];
        g_W3t[i] = __float2half_rn(w);
    }
}

// ---------------- FUSED layer 1: gather+mean -> smem A-tile -> HMMA ----------
// One CTA = 128 dst nodes. Phase 1: 8 warps gather 128x15 random x-rows (400 B)
// and build A[128][224] fp16 in smem (stride 232: 29*16B rows, 16-distinct-bank
// for ldmatrix). Phase 2: GEMM vs W1t over both 128-col halves of N=256.
// 2 CTAs/SM -> gather of one CTA overlaps MMA of the other.
namespace {
constexpr int A_STRIDE = 232;                       // fp16 elems per smem row
constexpr int SM_A_BYTES = 128 * A_STRIDE * 2;      // 59392
constexpr int SM_B_BYTES = 2 * 128 * 40 * 2;        // 20480
constexpr int SM1_TOTAL = SM_A_BYTES + SM_B_BYTES + 256 * 4;  // 80896
}

__global__ void __launch_bounds__(256, 2) fused1_kernel(
    const float* __restrict__ x, const void* __restrict__ src,
    const __half* __restrict__ Wt, const float* __restrict__ bias,
    __half* __restrict__ h1) {
    extern __shared__ char smem[];
    __half* smA = (__half*)smem;
    float* sbias = (float*)(smem + SM_A_BYTES + SM_B_BYTES);

    const int tid = threadIdx.x, wid = tid >> 5, lane = tid & 31;
    const size_t rowBase = (size_t)blockIdx.x * 128;
    const int is64 = g_is64;
    if (tid < 256) sbias[tid] = bias[tid];

    // ---- phase 1: gather + mean into smA ----
    const float4* x4 = (const float4*)x;  // 25 float4 per x-row
    for (int n = wid; n < 128; n += 8) {
        long long idx = 0;
        if (lane < 15) idx = load_index(src, (rowBase + n) * 15 + lane, is64);
        float4 acc = make_float4(0.f, 0.f, 0.f, 0.f);
#pragma unroll
        for (int j = 0; j < 15; ++j) {
            long long rr = __shfl_sync(0xffffffffu, idx, j);
            if (lane < 25) {
                float4 v = __ldg(&x4[rr * 25 + lane]);
                acc.x += v.x; acc.y += v.y; acc.z += v.z; acc.w += v.w;
            }
        }
        __half* row = smA + n * A_STRIDE;
        if (lane < 25) {
            const float inv = 1.0f / 15.0f;
            *(__half2*)(row + 4 * lane)     = __floats2half2_rn(acc.x * inv, acc.y * inv);
            *(__half2*)(row + 4 * lane + 2) = __floats2half2_rn(acc.z * inv, acc.w * inv);
            float4 d = __ldg(&x4[(rowBase + n) * 25 + lane]);
            *(__half2*)(row + 100 + 4 * lane)     = __floats2half2_rn(d.x, d.y);
            *(__half2*)(row + 100 + 4 * lane + 2) = __floats2half2_rn(d.z, d.w);
        }
        if (lane < 6) *(uint2*)(row + 200 + 4 * lane) = make_uint2(0u, 0u);
    }
    __syncthreads();

    // ---- phase 2: GEMM from resident smA, B streamed, two N-halves ----
    const uint32_t saA = smem_u32(smA);
    const uint32_t sbB0 = saA + SM_A_BYTES;
    const uint32_t sbB1 = sbB0 + 128 * 40 * 2;
    const int wm = wid & 3, wn = wid >> 2;
    const int m0 = wm * 32, n0 = wn * 64;
    const int r = lane >> 2, cp2 = (lane & 3) * 2;

#pragma unroll 1
    for (int h = 0; h < 2; ++h) {
        float acc[2][8][4];
#pragma unroll
        for (int mi = 0; mi < 2; ++mi)
#pragma unroll
            for (int ni = 0; ni < 8; ++ni)
#pragma unroll
                for (int q = 0; q < 4; ++q) acc[mi][ni][q] = 0.f;

        const __half* wsrc = Wt + (size_t)(h * 128) * K1P;
        auto loadB = [&](int it, uint32_t bbase) {
            const int k0 = it * 32;
#pragma unroll
            for (int t = 0; t < 2; ++t) {
                int c = tid + t * 256;
                int rw = c >> 2, kc = c & 3;
                cpasync16(bbase + rw * 80 + kc * 16, wsrc + (size_t)rw * K1P + k0 + kc * 8);
            }
            asm volatile("cp.async.commit_group;" ::: "memory");
        };

        loadB(0, sbB0);
        for (int i = 0; i < 7; ++i) {
            const uint32_t bb = (i & 1) ? sbB1 : sbB0;
            if (i + 1 < 7) {
                loadB(i + 1, (i & 1) ? sbB0 : sbB1);
                asm volatile("cp.async.wait_group 1;" ::: "memory");
            } else {
                asm volatile("cp.async.wait_group 0;" ::: "memory");
            }
            __syncthreads();
#pragma unroll
            for (int kk = 0; kk < 2; ++kk) {
                uint32_t af[2][4];
#pragma unroll
                for (int mi = 0; mi < 2; ++mi) {
                    uint32_t ad = saA + (uint32_t)((m0 + mi * 16 + (lane & 15)) * (A_STRIDE * 2) +
                                                   i * 64 + kk * 32 + (lane >> 4) * 16);
                    ldm_x4(af[mi][0], af[mi][1], af[mi][2], af[mi][3], ad);
                }
#pragma unroll
                for (int ni = 0; ni < 8; ++ni) {
                    uint32_t b0, b1;
                    uint32_t bd = bb + (uint32_t)((n0 + ni * 8 + (lane & 7)) * 80 +
                                                  kk * 32 + ((lane >> 3) & 1) * 16);
                    ldm_x2(b0, b1, bd);
#pragma unroll
                    for (int mi = 0; mi < 2; ++mi) mma16816(acc[mi][ni], af[mi], b0, b1);
                }
            }
            __syncthreads();
        }
        // epilogue: bias + relu, fp16 h1
#pragma unroll
        for (int mi = 0; mi < 2; ++mi) {
#pragma unroll
            for (int ni = 0; ni < 8; ++ni) {
                const int jl = n0 + ni * 8 + cp2;
                const int col = h * 128 + jl;
                const size_t row0 = rowBase + m0 + mi * 16 + r;
                float v0 = fmaxf(acc[mi][ni][0] + sbias[col], 0.f);
                float v1 = fmaxf(acc[mi][ni][1] + sbias[col + 1], 0.f);
                float v2 = fmaxf(acc[mi][ni][2] + sbias[col], 0.f);
                float v3 = fmaxf(acc[mi][ni][3] + sbias[col + 1], 0.f);
                *(__half2*)(h1 + row0 * 256 + col) = __floats2half2_rn(v0, v1);
                *(__half2*)(h1 + (row0 + 8) * 256 + col) = __floats2half2_rn(v2, v3);
            }
        }
    }
}

// ---------------- 256-wide fp16 aggregation (layers 2,3) ---------------------
template <int FAN>
__global__ void agg256_kernel(const __half* __restrict__ h, const void* __restrict__ src,
                              __half* __restrict__ A, int ndst) {
    int gw = (blockIdx.x * blockDim.x + threadIdx.x) >> 5;
    int lane = threadIdx.x & 31;
    if (gw >= ndst) return;
    const int is64 = g_is64;

    long long myidx = 0;
    if (lane < FAN) myidx = load_index(src, (long long)gw * FAN + lane, is64);

    const uint4* h4 = (const uint4*)h;  // 32 uint4 per row
    float acc[8];
#pragma unroll
    for (int t = 0; t < 8; ++t) acc[t] = 0.f;

#pragma unroll
    for (int j = 0; j < FAN; ++j) {
        long long rr = __shfl_sync(0xffffffffu, myidx, j);
        uint4 v = __ldg(&h4[rr * 32 + lane]);
        const __half2* hv = (const __half2*)&v;
#pragma unroll
        for (int q = 0; q < 4; ++q) {
            float2 f = __half22float2(hv[q]);
            acc[2 * q] += f.x;
            acc[2 * q + 1] += f.y;
        }
    }
    const float inv = 1.0f / (float)FAN;
    uint4 outv;
    __half2* ho = (__half2*)&outv;
#pragma unroll
    for (int q = 0; q < 4; ++q)
        ho[q] = __floats2half2_rn(acc[2 * q] * inv, acc[2 * q + 1] * inv);
    uint4* o = (uint4*)(A + (size_t)gw * K2P);
    o[lane] = outv;
    o[32 + lane] = __ldg(&h4[(size_t)gw * 32 + lane]);
}

// ---------------- HMMA GEMM (layers 2,3): out = A[M,K] @ Wt[N,K]^T -----------
template <int BN, int KP, bool RELU, bool FINAL>
__global__ void __launch_bounds__(256) mma_gemm(
    const __half* __restrict__ Ap, const __half* __restrict__ Wt,
    const float* __restrict__ bias, void* __restrict__ outv, int ntot) {
    constexpr int BM = 128;
    constexpr int LDS = 40;
    constexpr int NIT = KP / 32;
    constexpr int NI = BN / 16;

    __shared__ __half smA[2][BM * LDS];
    __shared__ __half smB[2][BN * LDS];
    __shared__ float sbias[BN];

    const int tid = threadIdx.x;
    const int wid = tid >> 5, lane = tid & 31;
    const int wm = wid & 3, wn = wid >> 2;
    const int m0 = wm * 32;
    const int n0 = wn * (BN / 2);
    const size_t rowBase = (size_t)blockIdx.y * BM;
    const int colBase = blockIdx.x * BN;

    if (tid < BN) sbias[tid] = (colBase + tid < ntot) ? bias[colBase + tid] : 0.f;

    const uint32_t sa0 = smem_u32(&smA[0][0]);
    const uint32_t sa1 = smem_u32(&smA[1][0]);
    const uint32_t sb0 = smem_u32(&smB[0][0]);
    const uint32_t sb1 = smem_u32(&smB[1][0]);

    float acc[2][NI][4];
#pragma unroll
    for (int mi = 0; mi < 2; ++mi)
#pragma unroll
        for (int ni = 0; ni < NI; ++ni)
#pragma unroll
            for (int q = 0; q < 4; ++q) acc[mi][ni][q] = 0.f;

    auto load_tile = [&](int it, int buf) {
        const int k0 = it * 32;
        const __half* srcp = Ap + rowBase * KP + k0;
        const uint32_t abase = buf ? sa1 : sa0;
#pragma unroll
        for (int t = 0; t < 2; ++t) {
            int c = tid + t * 256;
            int row = c >> 2, kc = c & 3;
            cpasync16(abase + row * (LDS * 2) + kc * 16, srcp + (size_t)row * KP + kc * 8);
        }
        const __half* wsrc = Wt + (size_t)colBase * KP + k0;
        const uint32_t bbase = buf ? sb1 : sb0;
#pragma unroll
        for (int t = 0; t < BN / 64; ++t) {
            int c = tid + t * 256;
            int row = c >> 2, kc = c & 3;
            cpasync16(bbase + row * (LDS * 2) + kc * 16, wsrc + (size_t)row * KP + kc * 8);
        }
        asm volatile("cp.async.commit_group;" ::: "memory");
    };

    load_tile(0, 0);
    for (int i = 0; i < NIT; ++i) {
        const int buf = i & 1;
        if (i + 1 < NIT) {
            load_tile(i + 1, buf ^ 1);
            asm volatile("cp.async.wait_group 1;" ::: "memory");
        } else {
            asm volatile("cp.async.wait_group 0;" ::: "memory");
        }
        __syncthreads();

        const uint32_t aA = buf ? sa1 : sa0;
        const uint32_t aB = buf ? sb1 : sb0;
#pragma unroll
        for (int kk = 0; kk < 2; ++kk) {
            uint32_t afr[2][4];
#pragma unroll
            for (int mi = 0; mi < 2; ++mi) {
                uint32_t ad = aA + (uint32_t)((m0 + mi * 16 + (lane & 15)) * (LDS * 2) +
                                              kk * 32 + (lane >> 4) * 16);
                ldm_x4(afr[mi][0], afr[mi][1], afr[mi][2], afr[mi][3], ad);
            }
#pragma unroll
            for (int ni = 0; ni < NI; ++ni) {
                uint32_t b0, b1;
                uint32_t bd = aB + (uint32_t)((n0 + ni * 8 + (lane & 7)) * (LDS * 2) +
                                              kk * 32 + ((lane >> 3) & 1) * 16);
                ldm_x2(b0, b1, bd);
#pragma unroll
                for (int mi = 0; mi < 2; ++mi) mma16816(acc[mi][ni], afr[mi], b0, b1);
            }
        }
        __syncthreads();
    }

    const int r = lane >> 2;
    const int cp = (lane & 3) * 2;
#pragma unroll
    for (int mi = 0; mi < 2; ++mi) {
#pragma unroll
        for (int ni = 0; ni < NI; ++ni) {
            const int jc = n0 + ni * 8 + cp;
            const int col = colBase + jc;
            const size_t row0 = rowBase + m0 + mi * 16 + r;
            float v0 = acc[mi][ni][0] + sbias[jc];
            float v1 = acc[mi][ni][1] + sbias[jc + 1];
            float v2 = acc[mi][ni][2] + sbias[jc];
            float v3 = acc[mi][ni][3] + sbias[jc + 1];
            if (RELU) {
                v0 = fmaxf(v0, 0.f); v1 = fmaxf(v1, 0.f);
                v2 = fmaxf(v2, 0.f); v3 = fmaxf(v3, 0.f);
            }
            if (FINAL) {
                float* out = (float*)outv;
                if (col < ntot) {
                    out[row0 * ntot + col] = v0;
                    out[(row0 + 8) * ntot + col] = v2;
                }
                if (col + 1 < ntot) {
                    out[row0 * ntot + col + 1] = v1;
                    out[(row0 + 8) * ntot + col + 1] = v3;
                }
            } else {
                __half* out = (__half*)outv;
                *(__half2*)(out + row0 * ntot + col) = __floats2half2_rn(v0, v1);
                *(__half2*)(out + (row0 + 8) * ntot + col) = __floats2half2_rn(v2, v3);
            }
        }
    }
}

// ---------------- log_softmax over 47 cols, warp per row, in place -----------
__global__ void logsoftmax_kernel(float* __restrict__ out) {
    int gw = (blockIdx.x * blockDim.x + threadIdx.x) >> 5;
    int lane = threadIdx.x & 31;
    if (gw >= kN3) return;
    float* row = out + (long long)gw * kOUT;
    float v0 = (lane < kOUT) ? row[lane] : -1e30f;
    float v1 = (lane + 32 < kOUT) ? row[lane + 32] : -1e30f;
    float m = fmaxf(v0, v1);
#pragma unroll
    for (int o = 16; o; o >>= 1) m = fmaxf(m, __shfl_xor_sync(0xffffffffu, m, o));
    float s = 0.f;
    if (lane < kOUT) s += expf(v0 - m);
    if (lane + 32 < kOUT) s += expf(v1 - m);
#pragma unroll
    for (int o = 16; o; o >>= 1) s += __shfl_xor_sync(0xffffffffu, s, o);
    float lse = m + logf(s);
    if (lane < kOUT) row[lane] = v0 - lse;
    if (lane + 32 < kOUT) row[lane + 32] = v1 - lse;
}

// ---------------- launch -----------------------------------------------------
extern "C" void kernel_launch(void* const* d_in, const int* in_sizes, int n_in,
                              void* d_out, int out_size) {
    const float* x   = (const float*)d_in[0];
    const float* Wl1 = (const float*)d_in[1];
    const float* Wr1 = (const float*)d_in[2];
    const float* b1  = (const float*)d_in[3];
    const float* Wl2 = (const float*)d_in[4];
    const float* Wr2 = (const float*)d_in[5];
    const float* b2  = (const float*)d_in[6];
    const float* Wl3 = (const float*)d_in[7];
    const float* Wr3 = (const float*)d_in[8];
    const float* b3  = (const float*)d_in[9];
    const void*  src1 = d_in[10];
    const void*  dst1 = d_in[11];
    const void*  src2 = d_in[12];
    const void*  src3 = d_in[14];
    float* out = (float*)d_out;

    __half *A2, *A3, *W1t, *W2t, *W3t, *h1, *h2;
    cudaGetSymbolAddress((void**)&A2, g_A2);
    cudaGetSymbolAddress((void**)&A3, g_A3);
    cudaGetSymbolAddress((void**)&W1t, g_W1t);
    cudaGetSymbolAddress((void**)&W2t, g_W2t);
    cudaGetSymbolAddress((void**)&W3t, g_W3t);
    cudaGetSymbolAddress((void**)&h1, g_h1);
    cudaGetSymbolAddress((void**)&h2, g_h2);

    cudaFuncSetAttribute((const void*)fused1_kernel,
                         cudaFuncAttributeMaxDynamicSharedMemorySize, SM1_TOTAL);

    // 1. pack weights + index-dtype detect
    pack_weights<<<(256 * K2P + 255) / 256, 256>>>(Wl1, Wr1, Wl2, Wr2, Wl3, Wr3, dst1);

    // 2. layer 1 (fused gather + GEMM)
    fused1_kernel<<<kN1 / 128, 256, SM1_TOTAL>>>(x, src1, W1t, b1, h1);

    // 3. layer 2
    agg256_kernel<kFAN2><<<kN2 / 8, 256>>>(h1, src2, A2, kN2);
    mma_gemm<128, K2P, true, false><<<dim3(2, kN2 / 128), 256>>>(A2, W2t, b2, h2, 256);

    // 4. layer 3 -> d_out logits
    agg256_kernel<kFAN3><<<kN3 / 8, 256>>>(h2, src3, A3, kN3);
    mma_gemm<64, K2P, false, true><<<dim3(1, kN3 / 128), 256>>>(A3, W3t, b3, out, kOUT);

    // 5. log_softmax in place
    logsoftmax_kernel<<<kN3 / 8, 256>>>(out);
}

// round 6
// speedup vs baseline: 1.1215x; 1.1215x over previous
#include <cuda_runtime.h>
#include <cuda_fp16.h>
#include <cstdint>
#include <cstddef>

// ---------------- problem constants ----------------
namespace {
constexpr int kN1 = 67584;
constexpr int kN2 = 6144;
constexpr int kN3 = 1024;
constexpr int kFIN = 100;
constexpr int kHID = 256;
constexpr int kOUT = 47;
constexpr int kFAN2 = 10;
constexpr int kFAN3 = 5;
constexpr int K1P = 224;   // layer-1 K padded (agg 100 | dst 100 | zeros 24)
constexpr int K2P = 512;   // layer-2/3 K (agg 256 | dst 256)
}  // namespace

// ---------------- scratch (device globals) ----------------------------------
__device__ __half g_A1[(size_t)kN1 * K1P];
__device__ __half g_h1[(size_t)kN1 * kHID];
__device__ __half g_A2[(size_t)kN2 * K2P];
__device__ __half g_h2[(size_t)kN2 * kHID];
__device__ __half g_A3[(size_t)kN3 * K2P];
__device__ __half g_W1t[(size_t)256 * K1P];   // [N][K], transposed
__device__ __half g_W2t[(size_t)256 * K2P];
__device__ __half g_W3t[(size_t)64  * K2P];
__device__ int g_is64;

// ---------------- PTX helpers ------------------------------------------------
__device__ __forceinline__ uint32_t smem_u32(const void* p) {
    uint32_t a;
    asm("{ .reg .u64 t; cvta.to.shared.u64 t, %1; cvt.u32.u64 %0, t; }" : "=r"(a) : "l"(p));
    return a;
}
__device__ __forceinline__ void cpasync16(uint32_t saddr, const void* g) {
    asm volatile("cp.async.cg.shared.global [%0], [%1], 16;" :: "r"(saddr), "l"(g) : "memory");
}
__device__ __forceinline__ void ldm_x4(uint32_t& r0, uint32_t& r1, uint32_t& r2, uint32_t& r3,
                                       uint32_t addr) {
    asm volatile("ldmatrix.sync.aligned.m8n8.x4.shared.b16 {%0,%1,%2,%3}, [%4];"
                 : "=r"(r0), "=r"(r1), "=r"(r2), "=r"(r3) : "r"(addr));
}
__device__ __forceinline__ void mma16816(float* c, const uint32_t* a, uint32_t b0, uint32_t b1) {
    asm volatile(
        "mma.sync.aligned.m16n8k16.row.col.f32.f16.f16.f32 "
        "{%0,%1,%2,%3}, {%4,%5,%6,%7}, {%8,%9}, {%0,%1,%2,%3};"
        : "+f"(c[0]), "+f"(c[1]), "+f"(c[2]), "+f"(c[3])
        : "r"(a[0]), "r"(a[1]), "r"(a[2]), "r"(a[3]), "r"(b0), "r"(b1));
}
__device__ __forceinline__ long long load_index(const void* p, long long i, int is64) {
    return is64 ? ((const long long*)p)[i] : (long long)((const int*)p)[i];
}

// ---------------- pack weights (fp16, transposed [N][K]) ---------------------
__global__ void pack_weights(const float* __restrict__ Wl1, const float* __restrict__ Wr1,
                             const float* __restrict__ Wl2, const float* __restrict__ Wr2,
                             const float* __restrict__ Wl3, const float* __restrict__ Wr3,
                             const void* __restrict__ dst1) {
    int i = blockIdx.x * blockDim.x + threadIdx.x;
    if (i == 0) g_is64 = (((const long long*)dst1)[15] == 1LL) ? 1 : 0;

    if (i < 256 * K1P) {  // W1t
        int n = i / K1P, k = i % K1P;
        float w = 0.f;
        if (k < kFIN) w = Wl1[k * kHID + n];
        else if (k < 2 * kFIN) w = Wr1[(k - kFIN) * kHID + n];
        g_W1t[i] = __float2half_rn(w);
    }
    if (i < 256 * K2P) {  // W2t
        int n = i / K2P, k = i % K2P;
        float w = (k < kHID) ? Wl2[k * kHID + n] : Wr2[(k - kHID) * kHID + n];
        g_W2t[i] = __float2half_rn(w);
    }
    if (i < 64 * K2P) {  // W3t (N padded 47 -> 64)
        int n = i / K2P, k = i % K2P;
        float w = 0.f;
        if (n < kOUT) w = (k < kHID) ? Wl3[k * kOUT + n] : Wr3[(k - kHID) * kOUT + n];
        g_W3t[i] = __float2half_rn(w);
    }
}

// ---------------- layer-1 aggregation: TWO dst nodes per warp ---------------
// Edge indices for node0 live in lanes 0..14, node1 in lanes 16..30.
// Doubles per-warp outstanding LDGs (latency hiding) vs one-node warps.
__global__ void agg1_kernel(const float* __restrict__ x, const void* __restrict__ src) {
    int gw = (blockIdx.x * blockDim.x + threadIdx.x) >> 5;   // warp id = node pair
    int lane = threadIdx.x & 31;
    long long n0 = (long long)gw * 2;
    if (n0 >= kN1) return;
    const int is64 = g_is64;

    long long idx = 0;
    int sub = lane >> 4;                 // 0: node0, 1: node1
    int el = lane & 15;
    if (el < 15) idx = load_index(src, (n0 + sub) * 15 + el, is64);

    const float4* x4 = (const float4*)x;  // 25 float4 per x-row
    float4 a0 = make_float4(0.f, 0.f, 0.f, 0.f);
    float4 a1 = make_float4(0.f, 0.f, 0.f, 0.f);
#pragma unroll
    for (int j = 0; j < 15; ++j) {
        long long r0 = __shfl_sync(0xffffffffu, idx, j);
        long long r1 = __shfl_sync(0xffffffffu, idx, 16 + j);
        if (lane < 25) {
            float4 v0 = __ldg(&x4[r0 * 25 + lane]);
            float4 v1 = __ldg(&x4[r1 * 25 + lane]);
            a0.x += v0.x; a0.y += v0.y; a0.z += v0.z; a0.w += v0.w;
            a1.x += v1.x; a1.y += v1.y; a1.z += v1.z; a1.w += v1.w;
        }
    }
    const float inv = 1.0f / 15.0f;
    __half* o0 = g_A1 + (size_t)n0 * K1P;
    __half* o1 = o0 + K1P;
    if (lane < 25) {
        *(__half2*)(o0 + 4 * lane)     = __floats2half2_rn(a0.x * inv, a0.y * inv);
        *(__half2*)(o0 + 4 * lane + 2) = __floats2half2_rn(a0.z * inv, a0.w * inv);
        *(__half2*)(o1 + 4 * lane)     = __floats2half2_rn(a1.x * inv, a1.y * inv);
        *(__half2*)(o1 + 4 * lane + 2) = __floats2half2_rn(a1.z * inv, a1.w * inv);
        float4 d0 = __ldg(&x4[n0 * 25 + lane]);
        float4 d1 = __ldg(&x4[(n0 + 1) * 25 + lane]);
        *(__half2*)(o0 + kFIN + 4 * lane)     = __floats2half2_rn(d0.x, d0.y);
        *(__half2*)(o0 + kFIN + 4 * lane + 2) = __floats2half2_rn(d0.z, d0.w);
        *(__half2*)(o1 + kFIN + 4 * lane)     = __floats2half2_rn(d1.x, d1.y);
        *(__half2*)(o1 + kFIN + 4 * lane + 2) = __floats2half2_rn(d1.z, d1.w);
    }
    if (lane < 6) {  // zero-pad cols 200..223
        *(uint2*)(o0 + 200 + 4 * lane) = make_uint2(0u, 0u);
        *(uint2*)(o1 + 200 + 4 * lane) = make_uint2(0u, 0u);
    }
}

// ---------------- 256-wide fp16 aggregation (layers 2,3) ---------------------
template <int FAN>
__global__ void agg256_kernel(const __half* __restrict__ h, const void* __restrict__ src,
                              __half* __restrict__ A, int ndst) {
    int gw = (blockIdx.x * blockDim.x + threadIdx.x) >> 5;
    int lane = threadIdx.x & 31;
    if (gw >= ndst) return;
    const int is64 = g_is64;

    long long myidx = 0;
    if (lane < FAN) myidx = load_index(src, (long long)gw * FAN + lane, is64);

    const uint4* h4 = (const uint4*)h;  // 32 uint4 per row
    float acc[8];
#pragma unroll
    for (int t = 0; t < 8; ++t) acc[t] = 0.f;

#pragma unroll
    for (int j = 0; j < FAN; ++j) {
        long long rr = __shfl_sync(0xffffffffu, myidx, j);
        uint4 v = __ldg(&h4[rr * 32 + lane]);
        const __half2* hv = (const __half2*)&v;
#pragma unroll
        for (int q = 0; q < 4; ++q) {
            float2 f = __half22float2(hv[q]);
            acc[2 * q] += f.x;
            acc[2 * q + 1] += f.y;
        }
    }
    const float inv = 1.0f / (float)FAN;
    uint4 outv;
    __half2* ho = (__half2*)&outv;
#pragma unroll
    for (int q = 0; q < 4; ++q)
        ho[q] = __floats2half2_rn(acc[2 * q] * inv, acc[2 * q + 1] * inv);
    uint4* o = (uint4*)(A + (size_t)gw * K2P);
    o[lane] = outv;
    o[32 + lane] = __ldg(&h4[(size_t)gw * 32 + lane]);
}

// ---------------- HMMA GEMM: out[M,Ntot] = A[M,K] @ Wt[Ntot,K]^T -------------
// Generic tile: BM x BN, 256 threads as WM x WN warp grid (WM*WN == 8).
// Warp tile: 32(m) x BN/WN(n). ldmatrix x4 only (A 2x, B in n-tile pairs).
// Smem stride 40 fp16 (80 B): ldmatrix conflict-free.
template <int BM, int BN, int WM, int WN, int KP, bool RELU, bool FINAL>
__global__ void __launch_bounds__(256) mma_gemm(
    const __half* __restrict__ Ap, const __half* __restrict__ Wt,
    const float* __restrict__ bias, void* __restrict__ outv, int ntot) {
    constexpr int LDS = 40;
    constexpr int NIT = KP / 32;
    constexpr int NI = BN / WN / 8;     // n8-tiles per warp (even)
    static_assert(WM * WN == 8 && (NI & 1) == 0 && BM / WM == 32, "cfg");

    __shared__ __half smA[2][BM * LDS];
    __shared__ __half smB[2][BN * LDS];
    __shared__ float sbias[BN];

    const int tid = threadIdx.x;
    const int wid = tid >> 5, lane = tid & 31;
    const int wm = wid % WM, wn = wid / WM;
    const int m0 = wm * 32;
    const int n0 = wn * (BN / WN);
    const size_t rowBase = (size_t)blockIdx.y * BM;
    const int colBase = blockIdx.x * BN;

    if (tid < BN) sbias[tid] = (colBase + tid < ntot) ? bias[colBase + tid] : 0.f;

    const uint32_t sa0 = smem_u32(&smA[0][0]);
    const uint32_t sa1 = smem_u32(&smA[1][0]);
    const uint32_t sb0 = smem_u32(&smB[0][0]);
    const uint32_t sb1 = smem_u32(&smB[1][0]);

    float acc[2][NI][4];
#pragma unroll
    for (int mi = 0; mi < 2; ++mi)
#pragma unroll
        for (int ni = 0; ni < NI; ++ni)
#pragma unroll
            for (int q = 0; q < 4; ++q) acc[mi][ni][q] = 0.f;

    auto load_tile = [&](int it, int buf) {
        const int k0 = it * 32;
        const __half* srcp = Ap + rowBase * KP + k0;
        const uint32_t abase = buf ? sa1 : sa0;
#pragma unroll
        for (int t = 0; t < BM * 4 / 256; ++t) {
            int c = tid + t * 256;
            int row = c >> 2, kc = c & 3;
            cpasync16(abase + row * (LDS * 2) + kc * 16, srcp + (size_t)row * KP + kc * 8);
        }
        const __half* wsrc = Wt + (size_t)colBase * KP + k0;
        const uint32_t bbase = buf ? sb1 : sb0;
#pragma unroll
        for (int t = 0; t < BN * 4 / 256; ++t) {
            int c = tid + t * 256;
            int row = c >> 2, kc = c & 3;
            cpasync16(bbase + row * (LDS * 2) + kc * 16, wsrc + (size_t)row * KP + kc * 8);
        }
        asm volatile("cp.async.commit_group;" ::: "memory");
    };

    load_tile(0, 0);
    for (int i = 0; i < NIT; ++i) {
        const int buf = i & 1;
        if (i + 1 < NIT) {
            load_tile(i + 1, buf ^ 1);
            asm volatile("cp.async.wait_group 1;" ::: "memory");
        } else {
            asm volatile("cp.async.wait_group 0;" ::: "memory");
        }
        __syncthreads();

        const uint32_t aA = buf ? sa1 : sa0;
        const uint32_t aB = buf ? sb1 : sb0;
#pragma unroll
        for (int kk = 0; kk < 2; ++kk) {
            uint32_t afr[2][4];
#pragma unroll
            for (int mi = 0; mi < 2; ++mi) {
                uint32_t ad = aA + (uint32_t)((m0 + mi * 16 + (lane & 15)) * (LDS * 2) +
                                              kk * 32 + (lane >> 4) * 16);
                ldm_x4(afr[mi][0], afr[mi][1], afr[mi][2], afr[mi][3], ad);
            }
            uint32_t bfr[NI][2];
#pragma unroll
            for (int p = 0; p < NI / 2; ++p) {  // pair of n8-tiles per ldmatrix.x4
                int row = n0 + p * 16 + ((lane >> 4) & 1) * 8 + (lane & 7);
                uint32_t bd = aB + (uint32_t)(row * (LDS * 2) +
                                              kk * 32 + ((lane >> 3) & 1) * 16);
                ldm_x4(bfr[2 * p][0], bfr[2 * p][1], bfr[2 * p + 1][0], bfr[2 * p + 1][1], bd);
            }
#pragma unroll
            for (int ni = 0; ni < NI; ++ni)
#pragma unroll
                for (int mi = 0; mi < 2; ++mi)
                    mma16816(acc[mi][ni], afr[mi], bfr[ni][0], bfr[ni][1]);
        }
        __syncthreads();
    }

    const int r = lane >> 2;
    const int cp = (lane & 3) * 2;
#pragma unroll
    for (int mi = 0; mi < 2; ++mi) {
#pragma unroll
        for (int ni = 0; ni < NI; ++ni) {
            const int jc = n0 + ni * 8 + cp;
            const int col = colBase + jc;
            const size_t row0 = rowBase + m0 + mi * 16 + r;
            float v0 = acc[mi][ni][0] + sbias[jc];
            float v1 = acc[mi][ni][1] + sbias[jc + 1];
            float v2 = acc[mi][ni][2] + sbias[jc];
            float v3 = acc[mi][ni][3] + sbias[jc + 1];
            if (RELU) {
                v0 = fmaxf(v0, 0.f); v1 = fmaxf(v1, 0.f);
                v2 = fmaxf(v2, 0.f); v3 = fmaxf(v3, 0.f);
            }
            if (FINAL) {
                float* out = (float*)outv;
                if (col < ntot) {
                    out[row0 * ntot + col] = v0;
                    out[(row0 + 8) * ntot + col] = v2;
                }
                if (col + 1 < ntot) {
                    out[row0 * ntot + col + 1] = v1;
                    out[(row0 + 8) * ntot + col + 1] = v3;
                }
            } else {
                __half* out = (__half*)outv;
                *(__half2*)(out + row0 * ntot + col) = __floats2half2_rn(v0, v1);
                *(__half2*)(out + (row0 + 8) * ntot + col) = __floats2half2_rn(v2, v3);
            }
        }
    }
}

// ---------------- log_softmax over 47 cols, warp per row, in place -----------
__global__ void logsoftmax_kernel(float* __restrict__ out) {
    int gw = (blockIdx.x * blockDim.x + threadIdx.x) >> 5;
    int lane = threadIdx.x & 31;
    if (gw >= kN3) return;
    float* row = out + (long long)gw * kOUT;
    float v0 = (lane < kOUT) ? row[lane] : -1e30f;
    float v1 = (lane + 32 < kOUT) ? row[lane + 32] : -1e30f;
    float m = fmaxf(v0, v1);
#pragma unroll
    for (int o = 16; o; o >>= 1) m = fmaxf(m, __shfl_xor_sync(0xffffffffu, m, o));
    float s = 0.f;
    if (lane < kOUT) s += expf(v0 - m);
    if (lane + 32 < kOUT) s += expf(v1 - m);
#pragma unroll
    for (int o = 16; o; o >>= 1) s += __shfl_xor_sync(0xffffffffu, s, o);
    float lse = m + logf(s);
    if (lane < kOUT) row[lane] = v0 - lse;
    if (lane + 32 < kOUT) row[lane + 32] = v1 - lse;
}

// ---------------- launch -----------------------------------------------------
extern "C" void kernel_launch(void* const* d_in, const int* in_sizes, int n_in,
                              void* d_out, int out_size) {
    const float* x   = (const float*)d_in[0];
    const float* Wl1 = (const float*)d_in[1];
    const float* Wr1 = (const float*)d_in[2];
    const float* b1  = (const float*)d_in[3];
    const float* Wl2 = (const float*)d_in[4];
    const float* Wr2 = (const float*)d_in[5];
    const float* b2  = (const float*)d_in[6];
    const float* Wl3 = (const float*)d_in[7];
    const float* Wr3 = (const float*)d_in[8];
    const float* b3  = (const float*)d_in[9];
    const void*  src1 = d_in[10];
    const void*  dst1 = d_in[11];
    const void*  src2 = d_in[12];
    const void*  src3 = d_in[14];
    float* out = (float*)d_out;

    __half *A1, *A2, *A3, *W1t, *W2t, *W3t, *h1, *h2;
    cudaGetSymbolAddress((void**)&A1, g_A1);
    cudaGetSymbolAddress((void**)&A2, g_A2);
    cudaGetSymbolAddress((void**)&A3, g_A3);
    cudaGetSymbolAddress((void**)&W1t, g_W1t);
    cudaGetSymbolAddress((void**)&W2t, g_W2t);
    cudaGetSymbolAddress((void**)&W3t, g_W3t);
    cudaGetSymbolAddress((void**)&h1, g_h1);
    cudaGetSymbolAddress((void**)&h2, g_h2);

    // 1. pack weights + index-dtype detect
    pack_weights<<<(256 * K2P + 255) / 256, 256>>>(Wl1, Wr1, Wl2, Wr2, Wl3, Wr3, dst1);

    // 2. layer 1 (two nodes per warp: kN1/2 warps)
    agg1_kernel<<<kN1 / 16, 256>>>(x, src1);
    mma_gemm<128, 128, 4, 2, K1P, true, false>
        <<<dim3(2, kN1 / 128), 256>>>(A1, W1t, b1, h1, 256);

    // 3. layer 2 (BM=64 -> 192 CTAs for SM coverage)
    agg256_kernel<kFAN2><<<kN2 / 8, 256>>>(h1, src2, A2, kN2);
    mma_gemm<64, 128, 2, 4, K2P, true, false>
        <<<dim3(2, kN2 / 64), 256>>>(A2, W2t, b2, h2, 256);

    // 4. layer 3 -> d_out logits (BM=64 -> 16 CTAs)
    agg256_kernel<kFAN3><<<kN3 / 8, 256>>>(h2, src3, A3, kN3);
    mma_gemm<64, 64, 2, 4, K2P, false, true>
        <<<dim3(1, kN3 / 64), 256>>>(A3, W3t, b3, out, kOUT);

    // 5. log_softmax in place
    logsoftmax_kernel<<<kN3 / 8, 256>>>(out);
}

// round 7
// speedup vs baseline: 1.1482x; 1.0239x over previous
#include <cuda_runtime.h>
#include <cuda_fp16.h>
#include <cstdint>
#include <cstddef>

// ---------------- problem constants ----------------
namespace {
constexpr int kN1 = 67584;
constexpr int kN2 = 6144;
constexpr int kN3 = 1024;
constexpr int kFIN = 100;
constexpr int kHID = 256;
constexpr int kOUT = 47;
constexpr int kFAN2 = 10;
constexpr int kFAN3 = 5;
constexpr int K1P = 256;   // layer-1 K padded (agg 100 | dst 100 | zeros 56)
constexpr int K2P = 512;   // layer-2/3 K (agg 256 | dst 256)
}  // namespace

// ---------------- scratch (device globals) ----------------------------------
__device__ __half g_A1[(size_t)kN1 * K1P];
__device__ __half g_h1[(size_t)kN1 * kHID];
__device__ __half g_A2[(size_t)kN2 * K2P];
__device__ __half g_h2[(size_t)kN2 * kHID];
__device__ __half g_A3[(size_t)kN3 * K2P];
__device__ __half g_W1t[(size_t)256 * K1P];   // [N][K], transposed
__device__ __half g_W2t[(size_t)256 * K2P];
__device__ __half g_W3t[(size_t)64  * K2P];
__device__ int g_is64;

// ---------------- PTX helpers ------------------------------------------------
__device__ __forceinline__ uint32_t smem_u32(const void* p) {
    uint32_t a;
    asm("{ .reg .u64 t; cvta.to.shared.u64 t, %1; cvt.u32.u64 %0, t; }" : "=r"(a) : "l"(p));
    return a;
}
__device__ __forceinline__ void cpasync16(uint32_t saddr, const void* g) {
    asm volatile("cp.async.cg.shared.global [%0], [%1], 16;" :: "r"(saddr), "l"(g) : "memory");
}
__device__ __forceinline__ void ldm_x4(uint32_t& r0, uint32_t& r1, uint32_t& r2, uint32_t& r3,
                                       uint32_t addr) {
    asm volatile("ldmatrix.sync.aligned.m8n8.x4.shared.b16 {%0,%1,%2,%3}, [%4];"
                 : "=r"(r0), "=r"(r1), "=r"(r2), "=r"(r3) : "r"(addr));
}
__device__ __forceinline__ void mma16816(float* c, const uint32_t* a, uint32_t b0, uint32_t b1) {
    asm volatile(
        "mma.sync.aligned.m16n8k16.row.col.f32.f16.f16.f32 "
        "{%0,%1,%2,%3}, {%4,%5,%6,%7}, {%8,%9}, {%0,%1,%2,%3};"
        : "+f"(c[0]), "+f"(c[1]), "+f"(c[2]), "+f"(c[3])
        : "r"(a[0]), "r"(a[1]), "r"(a[2]), "r"(a[3]), "r"(b0), "r"(b1));
}
__device__ __forceinline__ long long load_index(const void* p, long long i, int is64) {
    return is64 ? ((const long long*)p)[i] : (long long)((const int*)p)[i];
}

// ---------------- pack weights (fp16, transposed [N][K]) ---------------------
__global__ void pack_weights(const float* __restrict__ Wl1, const float* __restrict__ Wr1,
                             const float* __restrict__ Wl2, const float* __restrict__ Wr2,
                             const float* __restrict__ Wl3, const float* __restrict__ Wr3,
                             const void* __restrict__ dst1) {
    int i = blockIdx.x * blockDim.x + threadIdx.x;
    if (i == 0) g_is64 = (((const long long*)dst1)[15] == 1LL) ? 1 : 0;

    if (i < 256 * K1P) {  // W1t (zeros for k >= 200)
        int n = i / K1P, k = i % K1P;
        float w = 0.f;
        if (k < kFIN) w = Wl1[k * kHID + n];
        else if (k < 2 * kFIN) w = Wr1[(k - kFIN) * kHID + n];
        g_W1t[i] = __float2half_rn(w);
    }
    if (i < 256 * K2P) {  // W2t
        int n = i / K2P, k = i % K2P;
        float w = (k < kHID) ? Wl2[k * kHID + n] : Wr2[(k - kHID) * kHID + n];
        g_W2t[i] = __float2half_rn(w);
    }
    if (i < 64 * K2P) {  // W3t (N padded 47 -> 64)
        int n = i / K2P, k = i % K2P;
        float w = 0.f;
        if (n < kOUT) w = (k < kHID) ? Wl3[k * kOUT + n] : Wr3[(k - kHID) * kOUT + n];
        g_W3t[i] = __float2half_rn(w);
    }
}

// ---------------- layer-1 aggregation: 2 nodes/warp, MLP-batched loads -------
// Edge indices for node0 in lanes 0..14, node1 in lanes 16..30.
// Gathers batched 5-deep into registers before accumulation (MLP >= 10/lane).
__global__ void agg1_kernel(const float* __restrict__ x, const void* __restrict__ src) {
    int gw = (blockIdx.x * blockDim.x + threadIdx.x) >> 5;   // warp id = node pair
    int lane = threadIdx.x & 31;
    long long n0 = (long long)gw * 2;
    if (n0 >= kN1) return;
    const int is64 = g_is64;

    long long idx = 0;
    int sub = lane >> 4;
    int el = lane & 15;
    if (el < 15) idx = load_index(src, (n0 + sub) * 15 + el, is64);

    const float4* x4 = (const float4*)x;  // 25 float4 per x-row
    float4 a0 = make_float4(0.f, 0.f, 0.f, 0.f);
    float4 a1 = make_float4(0.f, 0.f, 0.f, 0.f);
#pragma unroll
    for (int jb = 0; jb < 3; ++jb) {
        float4 u[5], w[5];
#pragma unroll
        for (int t = 0; t < 5; ++t) {
            long long r0 = __shfl_sync(0xffffffffu, idx, jb * 5 + t);
            long long r1 = __shfl_sync(0xffffffffu, idx, 16 + jb * 5 + t);
            if (lane < 25) {
                u[t] = __ldg(&x4[r0 * 25 + lane]);
                w[t] = __ldg(&x4[r1 * 25 + lane]);
            }
        }
        if (lane < 25) {
#pragma unroll
            for (int t = 0; t < 5; ++t) {
                a0.x += u[t].x; a0.y += u[t].y; a0.z += u[t].z; a0.w += u[t].w;
                a1.x += w[t].x; a1.y += w[t].y; a1.z += w[t].z; a1.w += w[t].w;
            }
        }
    }
    const float inv = 1.0f / 15.0f;
    __half* o0 = g_A1 + (size_t)n0 * K1P;
    __half* o1 = o0 + K1P;
    if (lane < 25) {
        *(__half2*)(o0 + 4 * lane)     = __floats2half2_rn(a0.x * inv, a0.y * inv);
        *(__half2*)(o0 + 4 * lane + 2) = __floats2half2_rn(a0.z * inv, a0.w * inv);
        *(__half2*)(o1 + 4 * lane)     = __floats2half2_rn(a1.x * inv, a1.y * inv);
        *(__half2*)(o1 + 4 * lane + 2) = __floats2half2_rn(a1.z * inv, a1.w * inv);
        float4 d0 = __ldg(&x4[n0 * 25 + lane]);
        float4 d1 = __ldg(&x4[(n0 + 1) * 25 + lane]);
        *(__half2*)(o0 + kFIN + 4 * lane)     = __floats2half2_rn(d0.x, d0.y);
        *(__half2*)(o0 + kFIN + 4 * lane + 2) = __floats2half2_rn(d0.z, d0.w);
        *(__half2*)(o1 + kFIN + 4 * lane)     = __floats2half2_rn(d1.x, d1.y);
        *(__half2*)(o1 + kFIN + 4 * lane + 2) = __floats2half2_rn(d1.z, d1.w);
    }
    if (lane < 14) {  // zero-pad cols 200..255
        *(uint2*)(o0 + 200 + 4 * lane) = make_uint2(0u, 0u);
        *(uint2*)(o1 + 200 + 4 * lane) = make_uint2(0u, 0u);
    }
}

// ---------------- 256-wide fp16 aggregation (layers 2,3), MLP-batched --------
template <int FAN>
__global__ void agg256_kernel(const __half* __restrict__ h, const void* __restrict__ src,
                              __half* __restrict__ A, int ndst) {
    static_assert(FAN % 5 == 0, "fan");
    int gw = (blockIdx.x * blockDim.x + threadIdx.x) >> 5;
    int lane = threadIdx.x & 31;
    if (gw >= ndst) return;
    const int is64 = g_is64;

    long long myidx = 0;
    if (lane < FAN) myidx = load_index(src, (long long)gw * FAN + lane, is64);

    const uint4* h4 = (const uint4*)h;  // 32 uint4 per row
    float acc[8];
#pragma unroll
    for (int t = 0; t < 8; ++t) acc[t] = 0.f;

#pragma unroll
    for (int jb = 0; jb < FAN / 5; ++jb) {
        uint4 v[5];
#pragma unroll
        for (int t = 0; t < 5; ++t) {
            long long rr = __shfl_sync(0xffffffffu, myidx, jb * 5 + t);
            v[t] = __ldg(&h4[rr * 32 + lane]);
        }
#pragma unroll
        for (int t = 0; t < 5; ++t) {
            const __half2* hv = (const __half2*)&v[t];
#pragma unroll
            for (int q = 0; q < 4; ++q) {
                float2 f = __half22float2(hv[q]);
                acc[2 * q] += f.x;
                acc[2 * q + 1] += f.y;
            }
        }
    }
    const float inv = 1.0f / (float)FAN;
    uint4 outv;
    __half2* ho = (__half2*)&outv;
#pragma unroll
    for (int q = 0; q < 4; ++q)
        ho[q] = __floats2half2_rn(acc[2 * q] * inv, acc[2 * q + 1] * inv);
    uint4* o = (uint4*)(A + (size_t)gw * K2P);
    o[lane] = outv;
    o[32 + lane] = __ldg(&h4[(size_t)gw * 32 + lane]);
}

// ---------------- HMMA GEMM: out[M,Ntot] = A[M,K] @ Wt[Ntot,K]^T -------------
// BK=64, double-buffered. 256 threads as WM x WN warp grid (WM*WN == 8).
// Smem stride 72 fp16 (144 B): ldmatrix conflict-free (9r mod 8 = r).
template <int BM, int BN, int WM, int WN, int KP, bool RELU, bool FINAL>
__global__ void __launch_bounds__(256, 2) mma_gemm(
    const __half* __restrict__ Ap, const __half* __restrict__ Wt,
    const float* __restrict__ bias, void* __restrict__ outv, int ntot) {
    constexpr int LDS = 72;             // fp16 elems per smem row (BK=64 + pad 8)
    constexpr int NIT = KP / 64;
    constexpr int NI = BN / WN / 8;     // n8-tiles per warp (even)
    static_assert(WM * WN == 8 && (NI & 1) == 0 && BM / WM == 32 && KP % 64 == 0, "cfg");

    __shared__ __half smA[2][BM * LDS];
    __shared__ __half smB[2][BN * LDS];
    __shared__ float sbias[BN];

    const int tid = threadIdx.x;
    const int wid = tid >> 5, lane = tid & 31;
    const int wm = wid % WM, wn = wid / WM;
    const int m0 = wm * 32;
    const int n0 = wn * (BN / WN);
    const size_t rowBase = (size_t)blockIdx.y * BM;
    const int colBase = blockIdx.x * BN;

    if (tid < BN) sbias[tid] = (colBase + tid < ntot) ? bias[colBase + tid] : 0.f;

    const uint32_t sa0 = smem_u32(&smA[0][0]);
    const uint32_t sa1 = smem_u32(&smA[1][0]);
    const uint32_t sb0 = smem_u32(&smB[0][0]);
    const uint32_t sb1 = smem_u32(&smB[1][0]);

    float acc[2][NI][4];
#pragma unroll
    for (int mi = 0; mi < 2; ++mi)
#pragma unroll
        for (int ni = 0; ni < NI; ++ni)
#pragma unroll
            for (int q = 0; q < 4; ++q) acc[mi][ni][q] = 0.f;

    auto load_tile = [&](int it, int buf) {
        const int k0 = it * 64;
        const __half* srcp = Ap + rowBase * KP + k0;
        const uint32_t abase = buf ? sa1 : sa0;
#pragma unroll
        for (int t = 0; t < BM * 8 / 256; ++t) {   // BM x 64 fp16 = BM*8 chunks
            int c = tid + t * 256;
            int row = c >> 3, kc = c & 7;
            cpasync16(abase + row * (LDS * 2) + kc * 16, srcp + (size_t)row * KP + kc * 8);
        }
        const __half* wsrc = Wt + (size_t)colBase * KP + k0;
        const uint32_t bbase = buf ? sb1 : sb0;
#pragma unroll
        for (int t = 0; t < BN * 8 / 256; ++t) {
            int c = tid + t * 256;
            int row = c >> 3, kc = c & 7;
            cpasync16(bbase + row * (LDS * 2) + kc * 16, wsrc + (size_t)row * KP + kc * 8);
        }
        asm volatile("cp.async.commit_group;" ::: "memory");
    };

    load_tile(0, 0);
    for (int i = 0; i < NIT; ++i) {
        const int buf = i & 1;
        if (i + 1 < NIT) {
            load_tile(i + 1, buf ^ 1);
            asm volatile("cp.async.wait_group 1;" ::: "memory");
        } else {
            asm volatile("cp.async.wait_group 0;" ::: "memory");
        }
        __syncthreads();

        const uint32_t aA = buf ? sa1 : sa0;
        const uint32_t aB = buf ? sb1 : sb0;
#pragma unroll
        for (int kk = 0; kk < 4; ++kk) {
            uint32_t afr[2][4];
#pragma unroll
            for (int mi = 0; mi < 2; ++mi) {
                uint32_t ad = aA + (uint32_t)((m0 + mi * 16 + (lane & 15)) * (LDS * 2) +
                                              kk * 32 + (lane >> 4) * 16);
                ldm_x4(afr[mi][0], afr[mi][1], afr[mi][2], afr[mi][3], ad);
            }
            uint32_t bfr[NI][2];
#pragma unroll
            for (int p = 0; p < NI / 2; ++p) {  // pair of n8-tiles per ldmatrix.x4
                int row = n0 + p * 16 + ((lane >> 4) & 1) * 8 + (lane & 7);
                uint32_t bd = aB + (uint32_t)(row * (LDS * 2) +
                                              kk * 32 + ((lane >> 3) & 1) * 16);
                ldm_x4(bfr[2 * p][0], bfr[2 * p][1], bfr[2 * p + 1][0], bfr[2 * p + 1][1], bd);
            }
#pragma unroll
            for (int ni = 0; ni < NI; ++ni)
#pragma unroll
                for (int mi = 0; mi < 2; ++mi)
                    mma16816(acc[mi][ni], afr[mi], bfr[ni][0], bfr[ni][1]);
        }
        __syncthreads();
    }

    const int r = lane >> 2;
    const int cp = (lane & 3) * 2;
#pragma unroll
    for (int mi = 0; mi < 2; ++mi) {
#pragma unroll
        for (int ni = 0; ni < NI; ++ni) {
            const int jc = n0 + ni * 8 + cp;
            const int col = colBase + jc;
            const size_t row0 = rowBase + m0 + mi * 16 + r;
            float v0 = acc[mi][ni][0] + sbias[jc];
            float v1 = acc[mi][ni][1] + sbias[jc + 1];
            float v2 = acc[mi][ni][2] + sbias[jc];
            float v3 = acc[mi][ni][3] + sbias[jc + 1];
            if (RELU) {
                v0 = fmaxf(v0, 0.f); v1 = fmaxf(v1, 0.f);
                v2 = fmaxf(v2, 0.f); v3 = fmaxf(v3, 0.f);
            }
            if (FINAL) {
                float* out = (float*)outv;
                if (col < ntot) {
                    out[row0 * ntot + col] = v0;
                    out[(row0 + 8) * ntot + col] = v2;
                }
                if (col + 1 < ntot) {
                    out[row0 * ntot + col + 1] = v1;
                    out[(row0 + 8) * ntot + col + 1] = v3;
                }
            } else {
                __half* out = (__half*)outv;
                *(__half2*)(out + row0 * ntot + col) = __floats2half2_rn(v0, v1);
                *(__half2*)(out + (row0 + 8) * ntot + col) = __floats2half2_rn(v2, v3);
            }
        }
    }
}

// ---------------- log_softmax over 47 cols, warp per row, in place -----------
__global__ void logsoftmax_kernel(float* __restrict__ out) {
    int gw = (blockIdx.x * blockDim.x + threadIdx.x) >> 5;
    int lane = threadIdx.x & 31;
    if (gw >= kN3) return;
    float* row = out + (long long)gw * kOUT;
    float v0 = (lane < kOUT) ? row[lane] : -1e30f;
    float v1 = (lane + 32 < kOUT) ? row[lane + 32] : -1e30f;
    float m = fmaxf(v0, v1);
#pragma unroll
    for (int o = 16; o; o >>= 1) m = fmaxf(m, __shfl_xor_sync(0xffffffffu, m, o));
    float s = 0.f;
    if (lane < kOUT) s += expf(v0 - m);
    if (lane + 32 < kOUT) s += expf(v1 - m);
#pragma unroll
    for (int o = 16; o; o >>= 1) s += __shfl_xor_sync(0xffffffffu, s, o);
    float lse = m + logf(s);
    if (lane < kOUT) row[lane] = v0 - lse;
    if (lane + 32 < kOUT) row[lane + 32] = v1 - lse;
}

// ---------------- launch -----------------------------------------------------
extern "C" void kernel_launch(void* const* d_in, const int* in_sizes, int n_in,
                              void* d_out, int out_size) {
    const float* x   = (const float*)d_in[0];
    const float* Wl1 = (const float*)d_in[1];
    const float* Wr1 = (const float*)d_in[2];
    const float* b1  = (const float*)d_in[3];
    const float* Wl2 = (const float*)d_in[4];
    const float* Wr2 = (const float*)d_in[5];
    const float* b2  = (const float*)d_in[6];
    const float* Wl3 = (const float*)d_in[7];
    const float* Wr3 = (const float*)d_in[8];
    const float* b3  = (const float*)d_in[9];
    const void*  src1 = d_in[10];
    const void*  dst1 = d_in[11];
    const void*  src2 = d_in[12];
    const void*  src3 = d_in[14];
    float* out = (float*)d_out;

    __half *A1, *A2, *A3, *W1t, *W2t, *W3t, *h1, *h2;
    cudaGetSymbolAddress((void**)&A1, g_A1);
    cudaGetSymbolAddress((void**)&A2, g_A2);
    cudaGetSymbolAddress((void**)&A3, g_A3);
    cudaGetSymbolAddress((void**)&W1t, g_W1t);
    cudaGetSymbolAddress((void**)&W2t, g_W2t);
    cudaGetSymbolAddress((void**)&W3t, g_W3t);
    cudaGetSymbolAddress((void**)&h1, g_h1);
    cudaGetSymbolAddress((void**)&h2, g_h2);

    // 1. pack weights + index-dtype detect
    pack_weights<<<(256 * K2P + 255) / 256, 256>>>(Wl1, Wr1, Wl2, Wr2, Wl3, Wr3, dst1);

    // 2. layer 1 (two nodes per warp)
    agg1_kernel<<<kN1 / 16, 256>>>(x, src1);
    mma_gemm<128, 128, 4, 2, K1P, true, false>
        <<<dim3(2, kN1 / 128), 256>>>(A1, W1t, b1, h1, 256);

    // 3. layer 2 (BM=64 -> 192 CTAs)
    agg256_kernel<kFAN2><<<kN2 / 8, 256>>>(h1, src2, A2, kN2);
    mma_gemm<64, 128, 2, 4, K2P, true, false>
        <<<dim3(2, kN2 / 64), 256>>>(A2, W2t, b2, h2, 256);

    // 4. layer 3 -> d_out logits
    agg256_kernel<kFAN3><<<kN3 / 8, 256>>>(h2, src3, A3, kN3);
    mma_gemm<64, 64, 2, 4, K2P, false, true>
        <<<dim3(1, kN3 / 64), 256>>>(A3, W3t, b3, out, kOUT);

    // 5. log_softmax in place
    logsoftmax_kernel<<<kN3 / 8, 256>>>(out);
}